// round 8
// baseline (speedup 1.0000x reference)
#include <cuda_runtime.h>
#include <cuda_fp16.h>
#include <cstdint>
#include <cstddef>

#define N_NODES 8192
#define IN_DIM  256
#define OUT_DIM 128
#define ALPHA   0.2f
#define MT      32       // rows per CTA
#define KT      128      // j per tile
#define NTILES  (N_NODES / KT)   // 64
#define WPR     (N_NODES / 32)   // 256 mask words per row
#define NTHREADS 512

#define WS_STRIDE (KT + 8)       // 136 halves
#define BS_STRIDE (OUT_DIM + 8)  // 136 halves
#define WS_BYTES  (MT * WS_STRIDE * 2)    // 8704
#define BS_BYTES  (KT * BS_STRIDE * 2)    // 34816
#define SMEM_BYTES (2 * WS_BYTES + 2 * BS_BYTES)  // 87040 -> 2 CTAs/SM

#define WH_BLOCKS (N_NODES / 16)   // 512 GEMM blocks fused into k_pre

// named barriers for producer/consumer handshake
#define BAR_FULL0 1
#define BAR_FULL1 2
#define BAR_FREE0 3
#define BAR_FREE1 4
#define BAR_SYNC(id)   asm volatile("bar.sync %0, 512;"   :: "r"(id) : "memory")
#define BAR_ARRIVE(id) asm volatile("bar.arrive %0, 512;" :: "r"(id) : "memory")
#define MEMBAR_CTA()   asm volatile("membar.cta;" ::: "memory")

// Scratch (device globals: no allocation allowed)
__device__ __half   g_Whh [N_NODES * OUT_DIM];
__device__ uint32_t g_abits[N_NODES * WPR];     // 8 MB packed adjacency
__device__ float    g_f1 [N_NODES];
__device__ float    g_f2 [N_NODES];
__device__ float    g_c;

// ---------------------------------------------------------------------------
// Kernel 1 (fused): blocks [0,512): Wh = X@W + f1/f2;  blocks [512,...):
// pack one adjacency row to bits (int4 loads + nibble shfl-reduce).
// ---------------------------------------------------------------------------
__global__ __launch_bounds__(256) void k_pre(const float* __restrict__ X,
                                             const float* __restrict__ W,
                                             const float* __restrict__ a,
                                             const int* __restrict__ adj) {
    const int tid = threadIdx.x;

    if (blockIdx.x >= WH_BLOCKS) {
        // ---- pack: one row per block, 8 warps x 1024 ints via int4 ----
        const int row  = blockIdx.x - WH_BLOCKS;
        const int w    = tid >> 5;
        const int lane = tid & 31;
        const int4* src4 =
            reinterpret_cast<const int4*>(adj + (size_t)row * N_NODES + w * 1024);
        uint32_t myword = 0;
#pragma unroll
        for (int k = 0; k < 8; k++) {
            int4 v = src4[k * 32 + lane];
            uint32_t nib = (uint32_t)(v.x > 0) | ((uint32_t)(v.y > 0) << 1) |
                           ((uint32_t)(v.z > 0) << 2) | ((uint32_t)(v.w > 0) << 3);
            uint32_t key = nib << ((lane & 7) * 4);
            key |= __shfl_xor_sync(0xffffffffu, key, 1);
            key |= __shfl_xor_sync(0xffffffffu, key, 2);
            key |= __shfl_xor_sync(0xffffffffu, key, 4);
            if ((lane & 7) == k) myword = key;  // lane L: word for k=L&7, group g=L>>3
        }
        g_abits[(size_t)row * WPR + w * 32 + (lane & 7) * 4 + (lane >> 3)] = myword;
        return;
    }

    // ---- GEMM part: 16 rows of Wh per block ----
    __shared__ float xs[16][IN_DIM];
    const int i0 = blockIdx.x * 16;

    const float4* Xv  = reinterpret_cast<const float4*>(X + (size_t)i0 * IN_DIM);
    float4*       xsv = reinterpret_cast<float4*>(&xs[0][0]);
#pragma unroll
    for (int q = 0; q < 4; q++) xsv[tid + q * 256] = Xv[tid + q * 256];
    __syncthreads();

    const int cg = tid & 31;
    const int rp = tid >> 5;
    const int r0 = rp * 2, r1 = r0 + 1;
    const int c4 = cg * 4;

    const float4* Wv = reinterpret_cast<const float4*>(W);
    float4 acc0 = {0.f, 0.f, 0.f, 0.f};
    float4 acc1 = {0.f, 0.f, 0.f, 0.f};
#pragma unroll 8
    for (int k = 0; k < IN_DIM; k++) {
        float4 w  = Wv[k * 32 + cg];
        float  x0 = xs[r0][k];
        float  x1 = xs[r1][k];
        acc0.x = fmaf(x0, w.x, acc0.x); acc0.y = fmaf(x0, w.y, acc0.y);
        acc0.z = fmaf(x0, w.z, acc0.z); acc0.w = fmaf(x0, w.w, acc0.w);
        acc1.x = fmaf(x1, w.x, acc1.x); acc1.y = fmaf(x1, w.y, acc1.y);
        acc1.z = fmaf(x1, w.z, acc1.z); acc1.w = fmaf(x1, w.w, acc1.w);
    }
    {
        __half2 h00 = __floats2half2_rn(acc0.x, acc0.y);
        __half2 h01 = __floats2half2_rn(acc0.z, acc0.w);
        __half2 h10 = __floats2half2_rn(acc1.x, acc1.y);
        __half2 h11 = __floats2half2_rn(acc1.z, acc1.w);
        __half2* p0 = reinterpret_cast<__half2*>(g_Whh + (size_t)(i0 + r0) * OUT_DIM + c4);
        __half2* p1 = reinterpret_cast<__half2*>(g_Whh + (size_t)(i0 + r1) * OUT_DIM + c4);
        p0[0] = h00; p0[1] = h01;
        p1[0] = h10; p1[1] = h11;
    }
    float p1 = acc0.x * a[c4] + acc0.y * a[c4 + 1] + acc0.z * a[c4 + 2] + acc0.w * a[c4 + 3];
    float q1 = acc0.x * a[128 + c4] + acc0.y * a[128 + c4 + 1] +
               acc0.z * a[128 + c4 + 2] + acc0.w * a[128 + c4 + 3];
    float p2 = acc1.x * a[c4] + acc1.y * a[c4 + 1] + acc1.z * a[c4 + 2] + acc1.w * a[c4 + 3];
    float q2 = acc1.x * a[128 + c4] + acc1.y * a[128 + c4 + 1] +
               acc1.z * a[128 + c4 + 2] + acc1.w * a[128 + c4 + 3];
#pragma unroll
    for (int off = 16; off; off >>= 1) {
        p1 += __shfl_xor_sync(0xffffffffu, p1, off);
        q1 += __shfl_xor_sync(0xffffffffu, q1, off);
        p2 += __shfl_xor_sync(0xffffffffu, p2, off);
        q2 += __shfl_xor_sync(0xffffffffu, q2, off);
    }
    if (cg == 0) {
        g_f1[i0 + r0] = p1; g_f2[i0 + r0] = q1;
        g_f1[i0 + r1] = p2; g_f2[i0 + r1] = q2;
    }
}

__global__ __launch_bounds__(256) void k_max() {
    __shared__ float red[8];
    int t = threadIdx.x;
    float m = -1e30f;
    for (int i = t; i < N_NODES; i += 256) m = fmaxf(m, g_f2[i]);
#pragma unroll
    for (int off = 16; off; off >>= 1) m = fmaxf(m, __shfl_xor_sync(0xffffffffu, m, off));
    if ((t & 31) == 0) red[t >> 5] = m;
    __syncthreads();
    if (t == 0) {
        float mm = red[0];
#pragma unroll
        for (int i = 1; i < 8; i++) mm = fmaxf(mm, red[i]);
        g_c = mm;
    }
}

__device__ __forceinline__ uint32_t s2u(const void* p) {
    return (uint32_t)__cvta_generic_to_shared(p);
}
__device__ __forceinline__ void cpasync16(uint32_t dst, const void* src) {
    asm volatile("cp.async.cg.shared.global [%0], [%1], 16;\n" :: "r"(dst), "l"(src));
}
#define CP_COMMIT() asm volatile("cp.async.commit_group;\n" ::: "memory")
#define CP_WAIT0()  asm volatile("cp.async.wait_group 0;\n" ::: "memory")

__device__ __forceinline__ void mma16816(float* d, uint32_t a0, uint32_t a1, uint32_t a2,
                                         uint32_t a3, uint32_t b0, uint32_t b1) {
    asm volatile(
        "mma.sync.aligned.m16n8k16.row.col.f32.f16.f16.f32 "
        "{%0,%1,%2,%3},{%4,%5,%6,%7},{%8,%9},{%0,%1,%2,%3};\n"
        : "+f"(d[0]), "+f"(d[1]), "+f"(d[2]), "+f"(d[3])
        : "r"(a0), "r"(a1), "r"(a2), "r"(a3), "r"(b0), "r"(b1));
}

// generate 8 j-values of one W row from an 8-bit mask window
__device__ __forceinline__ void gen8(uint32_t byte_bits, int jt,
                                     __half (*WsB)[WS_STRIDE],
                                     int r, int jo, float f1r, float Mr,
                                     float& Spart) {
    const float* f2p = g_f2 + jt + jo * 8;
    float4 fa = *reinterpret_cast<const float4*>(f2p);
    float4 fb = *reinterpret_cast<const float4*>(f2p + 4);
    float s0 = f1r + fa.x, s1 = f1r + fa.y, s2 = f1r + fa.z, s3 = f1r + fa.w;
    float s4 = f1r + fb.x, s5 = f1r + fb.y, s6 = f1r + fb.z, s7 = f1r + fb.w;
    float w0 = (byte_bits & 1u)   ? __expf(fmaxf(s0, ALPHA * s0) - Mr) : 0.f;
    float w1 = (byte_bits & 2u)   ? __expf(fmaxf(s1, ALPHA * s1) - Mr) : 0.f;
    float w2 = (byte_bits & 4u)   ? __expf(fmaxf(s2, ALPHA * s2) - Mr) : 0.f;
    float w3 = (byte_bits & 8u)   ? __expf(fmaxf(s3, ALPHA * s3) - Mr) : 0.f;
    float w4 = (byte_bits & 16u)  ? __expf(fmaxf(s4, ALPHA * s4) - Mr) : 0.f;
    float w5 = (byte_bits & 32u)  ? __expf(fmaxf(s5, ALPHA * s5) - Mr) : 0.f;
    float w6 = (byte_bits & 64u)  ? __expf(fmaxf(s6, ALPHA * s6) - Mr) : 0.f;
    float w7 = (byte_bits & 128u) ? __expf(fmaxf(s7, ALPHA * s7) - Mr) : 0.f;
    __half2 h0 = __floats2half2_rn(w0, w1);
    __half2 h1 = __floats2half2_rn(w2, w3);
    __half2 h2 = __floats2half2_rn(w4, w5);
    __half2 h3 = __floats2half2_rn(w6, w7);
    *reinterpret_cast<uint4*>(&WsB[r][jo * 8]) =
        make_uint4(*reinterpret_cast<uint32_t*>(&h0), *reinterpret_cast<uint32_t*>(&h1),
                   *reinterpret_cast<uint32_t*>(&h2), *reinterpret_cast<uint32_t*>(&h3));
    // sum the fp16-ROUNDED values so numerator/denominator errors cancel
    float2 c0 = __half22float2(h0), c1 = __half22float2(h1);
    float2 c2 = __half22float2(h2), c3 = __half22float2(h3);
    Spart += ((c0.x + c0.y) + (c1.x + c1.y)) + ((c2.x + c2.y) + (c3.x + c3.y));
}

// ---------------------------------------------------------------------------
// Kernel 3: warp-specialized fused masked-softmax @ Wh.
// Warps 0-7: consumers (MMA, warp tile 16x32). Warps 8-15: producers
// (gen W tile + Bs cp.async + mask prefetch). Overlap via named barriers:
// FULL[b] (producers arrive, consumers sync), FREE[b] (consumers arrive,
// producers sync). gen(t) runs concurrently with MMA(t-1).
// ---------------------------------------------------------------------------
__global__ __launch_bounds__(NTHREADS, 2) void k_main(float* __restrict__ out) {
    extern __shared__ __align__(16) char smem[];
    __half(*WsA[2])[WS_STRIDE];
    __half(*BsA[2])[BS_STRIDE];
    WsA[0] = reinterpret_cast<__half(*)[WS_STRIDE]>(smem);
    WsA[1] = reinterpret_cast<__half(*)[WS_STRIDE]>(smem + WS_BYTES);
    BsA[0] = reinterpret_cast<__half(*)[BS_STRIDE]>(smem + 2 * WS_BYTES);
    BsA[1] = reinterpret_cast<__half(*)[BS_STRIDE]>(smem + 2 * WS_BYTES + BS_BYTES);

    const int tid  = threadIdx.x;
    const int lane = tid & 31, wid = tid >> 5;
    const int i0 = blockIdx.x * MT;
    float* Ssum = reinterpret_cast<float*>(smem);  // reused post-loop (32x8 floats)

    if (wid >= 8) {
        // ================= PRODUCER =================
        const int ptid = tid - 256;
        const int r    = ptid & 31;   // row 0..31
        const int jo2  = ptid >> 5;   // 0..7, 16 j each (two gen8 calls)
        // Bs cp.async: 2 threads per j-row, 64 halves each
        const int jb = ptid >> 1;
        const int bo = (ptid & 1) * 64;

        const float f1r = g_f1[i0 + r];
        const float gc  = g_c;
        const float sM  = f1r + gc;
        const float Mr  = fmaxf(sM, ALPHA * sM);

        const uint32_t bdst[2] = {s2u(&BsA[0][jb][bo]), s2u(&BsA[1][jb][bo])};
        const __half* bsrc_base = g_Whh + (size_t)jb * OUT_DIM + bo;

        const uint32_t* mrow = g_abits + (size_t)(i0 + r) * WPR + (jo2 >> 1);
        const int sh0 = ((jo2 & 1) * 2) * 8;     // first byte shift in word
        const int jA = jo2 * 2, jB = jo2 * 2 + 1;

        float Spart = 0.f;
        uint32_t mwCur = __ldg(mrow);   // word for tile 0

#pragma unroll 1
        for (int t = 0; t < NTILES; t++) {
            const int b = t & 1;
            if (t >= 2) BAR_SYNC(b ? BAR_FREE1 : BAR_FREE0);

            // async-load Bs tile t
            const __half* bsrc = bsrc_base + (size_t)t * KT * OUT_DIM;
#pragma unroll
            for (int q = 0; q < 8; q++) cpasync16(bdst[b] + q * 16, bsrc + q * 8);
            CP_COMMIT();

            // prefetch mask word for t+1
            uint32_t mwNext = (t + 1 < NTILES) ? __ldg(mrow + (size_t)(t + 1) * 4) : 0u;

            // generate W tile t (hides cp.async latency)
            gen8((mwCur >> sh0) & 0xffu, t * KT, WsA[b], r, jA, f1r, Mr, Spart);
            gen8((mwCur >> (sh0 + 8)) & 0xffu, t * KT, WsA[b], r, jB, f1r, Mr, Spart);
            mwCur = mwNext;

            CP_WAIT0();
            MEMBAR_CTA();
            BAR_ARRIVE(b ? BAR_FULL1 : BAR_FULL0);
        }

        __syncthreads();                 // consumers finished all MMA
        Ssum[r * 8 + jo2] = Spart;
        __syncthreads();
        // producers idle through output phase
    } else {
        // ================= CONSUMER =================
        const int wm = wid & 1;          // 2 row-slices of 16
        const int wn = wid >> 1;         // 4 col-slices of 32

        float acc[4][4];
#pragma unroll
        for (int n = 0; n < 4; n++)
#pragma unroll
            for (int e = 0; e < 4; e++) acc[n][e] = 0.f;

#pragma unroll 1
        for (int t = 0; t < NTILES; t++) {
            const int b = t & 1;
            BAR_SYNC(b ? BAR_FULL1 : BAR_FULL0);

            __half(*WsC)[WS_STRIDE] = WsA[b];
            __half(*BsC)[BS_STRIDE] = BsA[b];
#pragma unroll
            for (int ks = 0; ks < KT / 16; ks++) {
                uint32_t a0, a1, a2, a3;
                uint32_t aaddr = s2u(&WsC[wm * 16 + (lane & 15)][ks * 16 + (lane >> 4) * 8]);
                asm volatile("ldmatrix.sync.aligned.m8n8.x4.shared.b16 {%0,%1,%2,%3}, [%4];"
                             : "=r"(a0), "=r"(a1), "=r"(a2), "=r"(a3)
                             : "r"(aaddr));
#pragma unroll
                for (int half32 = 0; half32 < 2; half32++) {
                    uint32_t b0, b1, b2, b3;
                    uint32_t baddr = s2u(&BsC[ks * 16 + (lane & 15)]
                                             [wn * 32 + half32 * 16 + (lane >> 4) * 8]);
                    asm volatile(
                        "ldmatrix.sync.aligned.m8n8.x4.trans.shared.b16 {%0,%1,%2,%3}, [%4];"
                        : "=r"(b0), "=r"(b1), "=r"(b2), "=r"(b3)
                        : "r"(baddr));
                    mma16816(acc[half32 * 2],     a0, a1, a2, a3, b0, b1);
                    mma16816(acc[half32 * 2 + 1], a0, a1, a2, a3, b2, b3);
                }
            }

            BAR_ARRIVE(b ? BAR_FREE1 : BAR_FREE0);
        }

        __syncthreads();                 // producers store Ssum next
        __syncthreads();                 // Ssum visible

        const int g    = lane >> 2;
        const int row0 = wm * 16 + g;
        const int row1 = row0 + 8;
        float S0, S1;
        {
            const float4* p = reinterpret_cast<const float4*>(Ssum + row0 * 8);
            float4 sa = p[0], sb = p[1];
            S0 = (sa.x + sa.y + sa.z + sa.w) + (sb.x + sb.y + sb.z + sb.w);
            const float4* q = reinterpret_cast<const float4*>(Ssum + row1 * 8);
            float4 sc = q[0], sd = q[1];
            S1 = (sc.x + sc.y + sc.z + sc.w) + (sd.x + sd.y + sd.z + sd.w);
        }
        float inv0 = 1.f / S0, inv1 = 1.f / S1;

#pragma unroll
        for (int bn = 0; bn < 4; bn++) {
            int cn = wn * 32 + bn * 8 + 2 * (lane & 3);
            size_t o0 = (size_t)(i0 + row0) * OUT_DIM + cn;
            size_t o1 = (size_t)(i0 + row1) * OUT_DIM + cn;
            float v0 = acc[bn][0] * inv0, v1 = acc[bn][1] * inv0;
            float v2 = acc[bn][2] * inv1, v3 = acc[bn][3] * inv1;
            float2 r01 = make_float2(v0 > 0.f ? v0 : __expf(v0) - 1.f,
                                     v1 > 0.f ? v1 : __expf(v1) - 1.f);
            float2 r23 = make_float2(v2 > 0.f ? v2 : __expf(v2) - 1.f,
                                     v3 > 0.f ? v3 : __expf(v3) - 1.f);
            *reinterpret_cast<float2*>(out + o0) = r01;
            *reinterpret_cast<float2*>(out + o1) = r23;
        }
    }
}

// ---------------------------------------------------------------------------
extern "C" void kernel_launch(void* const* d_in, const int* in_sizes, int n_in,
                              void* d_out, int out_size) {
    const int*   adj = (const int*)d_in[0];
    const float* X   = (const float*)d_in[1];
    const float* W   = (const float*)d_in[2];
    const float* a   = (const float*)d_in[3];
    float* out = (float*)d_out;

    cudaFuncSetAttribute(k_main, cudaFuncAttributeMaxDynamicSharedMemorySize, SMEM_BYTES);

    k_pre<<<WH_BLOCKS + N_NODES, 256>>>(X, W, a, adj);
    k_max<<<1, 256>>>();
    k_main<<<N_NODES / MT, NTHREADS, SMEM_BYTES>>>(out);
}

// round 9
// speedup vs baseline: 1.1158x; 1.1158x over previous
#include <cuda_runtime.h>
#include <cuda_fp16.h>
#include <cstdint>
#include <cstddef>

#define N_NODES 8192
#define IN_DIM  256
#define OUT_DIM 128
#define ALPHA   0.2f
#define MT      32       // rows per CTA
#define KT      128      // j per tile
#define NTILES  (N_NODES / KT)   // 64
#define WPR     (N_NODES / 32)   // 256 mask words per row
#define NTHREADS 512

#define WS_STRIDE (KT + 8)       // 136 halves
#define BS_STRIDE (OUT_DIM + 8)  // 136 halves; col 128 = ones column for S
#define WS_BYTES  (MT * WS_STRIDE * 2)    // 8704
#define BS_BYTES  (KT * BS_STRIDE * 2)    // 34816
#define SMEM_BYTES (2 * WS_BYTES + 2 * BS_BYTES)  // 87040 -> 2 CTAs/SM

#define WH_BLOCKS (N_NODES / 16)   // 512 GEMM blocks fused into k_pre

// Scratch (device globals: no allocation allowed)
__device__ __half   g_Whh [N_NODES * OUT_DIM];
__device__ uint32_t g_abits[N_NODES * WPR];     // 8 MB packed adjacency
__device__ float    g_f1 [N_NODES];
__device__ float    g_f2 [N_NODES];
__device__ uint32_t g_P2 [N_NODES];             // half2(P_i,P_i), P_i = exp(f1_i - M_i)
__device__ uint32_t g_Q2 [N_NODES];             // half2(Q_i,Q_i), Q_i = exp(.2 f1_i - M_i)
__device__ __half   g_Uh [N_NODES];             // exp(f2_j)
__device__ __half   g_Vh [N_NODES];             // exp(.2 f2_j)
__device__ float    g_c;

// ---------------------------------------------------------------------------
// Kernel 1 (fused): blocks [0,512): Wh = X@W + f1/f2;  blocks [512,...):
// pack one adjacency row to bits (int4 loads + nibble shfl-reduce).
// ---------------------------------------------------------------------------
__global__ __launch_bounds__(256) void k_pre(const float* __restrict__ X,
                                             const float* __restrict__ W,
                                             const float* __restrict__ a,
                                             const int* __restrict__ adj) {
    const int tid = threadIdx.x;

    if (blockIdx.x >= WH_BLOCKS) {
        const int row  = blockIdx.x - WH_BLOCKS;
        const int w    = tid >> 5;
        const int lane = tid & 31;
        const int4* src4 =
            reinterpret_cast<const int4*>(adj + (size_t)row * N_NODES + w * 1024);
        uint32_t myword = 0;
#pragma unroll
        for (int k = 0; k < 8; k++) {
            int4 v = src4[k * 32 + lane];
            uint32_t nib = (uint32_t)(v.x > 0) | ((uint32_t)(v.y > 0) << 1) |
                           ((uint32_t)(v.z > 0) << 2) | ((uint32_t)(v.w > 0) << 3);
            uint32_t key = nib << ((lane & 7) * 4);
            key |= __shfl_xor_sync(0xffffffffu, key, 1);
            key |= __shfl_xor_sync(0xffffffffu, key, 2);
            key |= __shfl_xor_sync(0xffffffffu, key, 4);
            if ((lane & 7) == k) myword = key;
        }
        g_abits[(size_t)row * WPR + w * 32 + (lane & 7) * 4 + (lane >> 3)] = myword;
        return;
    }

    // ---- GEMM part: 16 rows of Wh per block ----
    __shared__ float xs[16][IN_DIM];
    const int i0 = blockIdx.x * 16;

    const float4* Xv  = reinterpret_cast<const float4*>(X + (size_t)i0 * IN_DIM);
    float4*       xsv = reinterpret_cast<float4*>(&xs[0][0]);
#pragma unroll
    for (int q = 0; q < 4; q++) xsv[tid + q * 256] = Xv[tid + q * 256];
    __syncthreads();

    const int cg = tid & 31;
    const int rp = tid >> 5;
    const int r0 = rp * 2, r1 = r0 + 1;
    const int c4 = cg * 4;

    const float4* Wv = reinterpret_cast<const float4*>(W);
    float4 acc0 = {0.f, 0.f, 0.f, 0.f};
    float4 acc1 = {0.f, 0.f, 0.f, 0.f};
#pragma unroll 8
    for (int k = 0; k < IN_DIM; k++) {
        float4 w  = Wv[k * 32 + cg];
        float  x0 = xs[r0][k];
        float  x1 = xs[r1][k];
        acc0.x = fmaf(x0, w.x, acc0.x); acc0.y = fmaf(x0, w.y, acc0.y);
        acc0.z = fmaf(x0, w.z, acc0.z); acc0.w = fmaf(x0, w.w, acc0.w);
        acc1.x = fmaf(x1, w.x, acc1.x); acc1.y = fmaf(x1, w.y, acc1.y);
        acc1.z = fmaf(x1, w.z, acc1.z); acc1.w = fmaf(x1, w.w, acc1.w);
    }
    {
        __half2 h00 = __floats2half2_rn(acc0.x, acc0.y);
        __half2 h01 = __floats2half2_rn(acc0.z, acc0.w);
        __half2 h10 = __floats2half2_rn(acc1.x, acc1.y);
        __half2 h11 = __floats2half2_rn(acc1.z, acc1.w);
        __half2* p0 = reinterpret_cast<__half2*>(g_Whh + (size_t)(i0 + r0) * OUT_DIM + c4);
        __half2* p1 = reinterpret_cast<__half2*>(g_Whh + (size_t)(i0 + r1) * OUT_DIM + c4);
        p0[0] = h00; p0[1] = h01;
        p1[0] = h10; p1[1] = h11;
    }
    float p1 = acc0.x * a[c4] + acc0.y * a[c4 + 1] + acc0.z * a[c4 + 2] + acc0.w * a[c4 + 3];
    float q1 = acc0.x * a[128 + c4] + acc0.y * a[128 + c4 + 1] +
               acc0.z * a[128 + c4 + 2] + acc0.w * a[128 + c4 + 3];
    float p2 = acc1.x * a[c4] + acc1.y * a[c4 + 1] + acc1.z * a[c4 + 2] + acc1.w * a[c4 + 3];
    float q2 = acc1.x * a[128 + c4] + acc1.y * a[128 + c4 + 1] +
               acc1.z * a[128 + c4 + 2] + acc1.w * a[128 + c4 + 3];
#pragma unroll
    for (int off = 16; off; off >>= 1) {
        p1 += __shfl_xor_sync(0xffffffffu, p1, off);
        q1 += __shfl_xor_sync(0xffffffffu, q1, off);
        p2 += __shfl_xor_sync(0xffffffffu, p2, off);
        q2 += __shfl_xor_sync(0xffffffffu, q2, off);
    }
    if (cg == 0) {
        g_f1[i0 + r0] = p1; g_f2[i0 + r0] = q1;
        g_f1[i0 + r1] = p2; g_f2[i0 + r1] = q2;
    }
}

__global__ __launch_bounds__(256) void k_max() {
    __shared__ float red[8];
    int t = threadIdx.x;
    float m = -1e30f;
    for (int i = t; i < N_NODES; i += 256) m = fmaxf(m, g_f2[i]);
#pragma unroll
    for (int off = 16; off; off >>= 1) m = fmaxf(m, __shfl_xor_sync(0xffffffffu, m, off));
    if ((t & 31) == 0) red[t >> 5] = m;
    __syncthreads();
    if (t == 0) {
        float mm = red[0];
#pragma unroll
        for (int i = 1; i < 8; i++) mm = fmaxf(mm, red[i]);
        g_c = mm;
    }
}

// ---------------------------------------------------------------------------
// Kernel 2b: separable softmax factors.
// exp(lrelu(x)-M) = max(P_i*U_j, Q_i*V_j) since exp is monotone and
// lrelu(x)=max(x, .2x) with x = f1_i + f2_j.
// ---------------------------------------------------------------------------
__global__ __launch_bounds__(256) void k_prep2() {
    int i = blockIdx.x * 256 + threadIdx.x;
    float f1 = g_f1[i], f2 = g_f2[i], c = g_c;
    float s = f1 + c;
    float M = fmaxf(s, ALPHA * s);          // >= lrelu(f1+f2_j) for all j
    __half P = __float2half_rn(__expf(f1 - M));
    __half Q = __float2half_rn(__expf(ALPHA * f1 - M));
    uint32_t pu = (uint32_t)__half_as_ushort(P);
    uint32_t qu = (uint32_t)__half_as_ushort(Q);
    g_P2[i] = pu | (pu << 16);
    g_Q2[i] = qu | (qu << 16);
    g_Uh[i] = __float2half_rn(__expf(f2));
    g_Vh[i] = __float2half_rn(__expf(ALPHA * f2));
}

__device__ __forceinline__ uint32_t s2u(const void* p) {
    return (uint32_t)__cvta_generic_to_shared(p);
}
__device__ __forceinline__ void cpasync16(uint32_t dst, const void* src) {
    asm volatile("cp.async.cg.shared.global [%0], [%1], 16;\n" :: "r"(dst), "l"(src));
}
#define CP_COMMIT() asm volatile("cp.async.commit_group;\n" ::: "memory")
#define CP_WAIT0()  asm volatile("cp.async.wait_group 0;\n" ::: "memory")

__device__ __forceinline__ void mma16816(float* d, uint32_t a0, uint32_t a1, uint32_t a2,
                                         uint32_t a3, uint32_t b0, uint32_t b1) {
    asm volatile(
        "mma.sync.aligned.m16n8k16.row.col.f32.f16.f16.f32 "
        "{%0,%1,%2,%3},{%4,%5,%6,%7},{%8,%9},{%0,%1,%2,%3};\n"
        : "+f"(d[0]), "+f"(d[1]), "+f"(d[2]), "+f"(d[3])
        : "r"(a0), "r"(a1), "r"(a2), "r"(a3), "r"(b0), "r"(b1));
}

// generate 8 j-values of one W row: w = mask & max(P*U, Q*V). Pure half2 +
// ALU, no MUFU, no fp32 loads. U/V are L1-resident fp16 (broadcast in warp).
__device__ __forceinline__ void gen8(uint32_t byte_bits, int jt,
                                     __half (*WsB)[WS_STRIDE],
                                     int r, int jo, uint32_t P2u, uint32_t Q2u) {
    const uint4 Uv = *reinterpret_cast<const uint4*>(g_Uh + jt + jo * 8);
    const uint4 Vv = *reinterpret_cast<const uint4*>(g_Vh + jt + jo * 8);
    // expand 8 mask bits -> 4 half2 bitmasks
    uint32_t rep = __byte_perm(byte_bits, 0, 0x0000);              // byte0 x4
    uint32_t m0  = __vcmpne4(rep & 0x08040201u, 0u);               // bits 0..3
    uint32_t m1  = __vcmpne4(rep & 0x80402010u, 0u);               // bits 4..7
    const __half2 P2 = *reinterpret_cast<const __half2*>(&P2u);
    const __half2 Q2 = *reinterpret_cast<const __half2*>(&Q2u);

    __half2 w0 = __hmax2(__hmul2(P2, *reinterpret_cast<const __half2*>(&Uv.x)),
                         __hmul2(Q2, *reinterpret_cast<const __half2*>(&Vv.x)));
    __half2 w1 = __hmax2(__hmul2(P2, *reinterpret_cast<const __half2*>(&Uv.y)),
                         __hmul2(Q2, *reinterpret_cast<const __half2*>(&Vv.y)));
    __half2 w2 = __hmax2(__hmul2(P2, *reinterpret_cast<const __half2*>(&Uv.z)),
                         __hmul2(Q2, *reinterpret_cast<const __half2*>(&Vv.z)));
    __half2 w3 = __hmax2(__hmul2(P2, *reinterpret_cast<const __half2*>(&Uv.w)),
                         __hmul2(Q2, *reinterpret_cast<const __half2*>(&Vv.w)));

    uint32_t o0 = *reinterpret_cast<uint32_t*>(&w0) & __byte_perm(m0, 0, 0x1100);
    uint32_t o1 = *reinterpret_cast<uint32_t*>(&w1) & __byte_perm(m0, 0, 0x3322);
    uint32_t o2 = *reinterpret_cast<uint32_t*>(&w2) & __byte_perm(m1, 0, 0x1100);
    uint32_t o3 = *reinterpret_cast<uint32_t*>(&w3) & __byte_perm(m1, 0, 0x3322);
    *reinterpret_cast<uint4*>(&WsB[r][jo * 8]) = make_uint4(o0, o1, o2, o3);
}

// ---------------------------------------------------------------------------
// Kernel 4: fused masked-softmax @ Wh, 512 threads, 2 CTAs/SM.
// Row sums come from an extra n=8 MMA against the ones-column (col 128) of
// Bs — exact fp32 sum of the same fp16 w used in the numerator.
// ---------------------------------------------------------------------------
__global__ __launch_bounds__(NTHREADS, 2) void k_main(float* __restrict__ out) {
    extern __shared__ __align__(16) char smem[];
    __half(*WsA[2])[WS_STRIDE];
    __half(*BsA[2])[BS_STRIDE];
    WsA[0] = reinterpret_cast<__half(*)[WS_STRIDE]>(smem);
    WsA[1] = reinterpret_cast<__half(*)[WS_STRIDE]>(smem + WS_BYTES);
    BsA[0] = reinterpret_cast<__half(*)[BS_STRIDE]>(smem + 2 * WS_BYTES);
    BsA[1] = reinterpret_cast<__half(*)[BS_STRIDE]>(smem + 2 * WS_BYTES + BS_BYTES);

    const int tid  = threadIdx.x;
    const int lane = tid & 31, wid = tid >> 5;
    const int wm = wid & 1;        // 2 row-slices of 16
    const int wn = wid >> 1;       // 8 col-slices of 16
    const int i0 = blockIdx.x * MT;

    // gen mapping
    const int r  = tid & 31;
    const int jo = tid >> 5;       // 16 chunks of 8 j
    // Bs cp.async mapping: 4 threads per j-row, 32 halves (4x16B) each
    const int jb = tid >> 2;
    const int bo = (tid & 3) * 32;

    const uint32_t P2u = g_P2[i0 + r];
    const uint32_t Q2u = g_Q2[i0 + r];

    const uint32_t bdst[2] = {s2u(&BsA[0][jb][bo]), s2u(&BsA[1][jb][bo])};
    const __half* bsrc_base = g_Whh + (size_t)jb * OUT_DIM + bo;

    // mask: word for tile t at mrow[t*4]; byte window = (jo&3)*8
    const uint32_t* mrow = g_abits + (size_t)(i0 + r) * WPR + (jo >> 2);
    const int msh = (jo & 3) * 8;

    float acc[2][4];
#pragma unroll
    for (int n = 0; n < 2; n++)
#pragma unroll
        for (int e = 0; e < 4; e++) acc[n][e] = 0.f;
    float acc_s[4] = {0.f, 0.f, 0.f, 0.f};   // used by warps 0,1 only

    // ones column init (cols 128..135 of both Bs buffers; cp.async never
    // touches them)
    if (tid < 256) {
        int b = tid >> 7, j = tid & 127;
        *reinterpret_cast<uint4*>(&BsA[b][j][128]) = make_uint4(0, 0, 0, 0);
        BsA[b][j][128] = __float2half(1.f);
    }

    // ---- prologue ----
    uint32_t mwA = __ldg(mrow);
    uint32_t mwB = __ldg(mrow + 4);
#pragma unroll
    for (int q = 0; q < 4; q++) cpasync16(bdst[0] + q * 16, bsrc_base + q * 8);
    CP_COMMIT();
    gen8((mwA >> msh) & 0xffu, 0, WsA[0], r, jo, P2u, Q2u);
    CP_WAIT0();
    __syncthreads();

#pragma unroll 1
    for (int cur = 0; cur < NTILES; cur++) {
        const int ph = cur & 1;

        // 1. commit Bs(cur+1)
        if (cur + 1 < NTILES) {
            const __half* bsrc = bsrc_base + (size_t)(cur + 1) * KT * OUT_DIM;
#pragma unroll
            for (int q = 0; q < 4; q++) cpasync16(bdst[ph ^ 1] + q * 16, bsrc + q * 8);
            CP_COMMIT();
        }
        // 2. prefetch mask word for tile cur+2
        uint32_t mwC = (cur + 2 < NTILES) ? __ldg(mrow + (size_t)(cur + 2) * 4) : 0u;

        // 3. MMA on current buffers (per warp: 16x16 out, 8 ks; warps 0,1
        //    additionally accumulate the ones-column row sums)
        __half(*WsC)[WS_STRIDE] = WsA[ph];
        __half(*BsC)[BS_STRIDE] = BsA[ph];
#pragma unroll
        for (int ks = 0; ks < KT / 16; ks++) {
            uint32_t a0, a1, a2, a3;
            uint32_t aaddr = s2u(&WsC[wm * 16 + (lane & 15)][ks * 16 + (lane >> 4) * 8]);
            asm volatile("ldmatrix.sync.aligned.m8n8.x4.shared.b16 {%0,%1,%2,%3}, [%4];"
                         : "=r"(a0), "=r"(a1), "=r"(a2), "=r"(a3)
                         : "r"(aaddr));
            uint32_t b0, b1, b2, b3;
            uint32_t baddr = s2u(&BsC[ks * 16 + (lane & 15)][wn * 16 + (lane >> 4) * 8]);
            asm volatile("ldmatrix.sync.aligned.m8n8.x4.trans.shared.b16 {%0,%1,%2,%3}, [%4];"
                         : "=r"(b0), "=r"(b1), "=r"(b2), "=r"(b3)
                         : "r"(baddr));
            mma16816(acc[0], a0, a1, a2, a3, b0, b1);
            mma16816(acc[1], a0, a1, a2, a3, b2, b3);
            if (wid < 2) {
                uint32_t s0, s1;
                uint32_t saddr = s2u(&BsC[ks * 16 + (lane & 15)][128]);
                asm volatile("ldmatrix.sync.aligned.m8n8.x2.trans.shared.b16 {%0,%1}, [%2];"
                             : "=r"(s0), "=r"(s1)
                             : "r"(saddr));
                mma16816(acc_s, a0, a1, a2, a3, s0, s1);
            }
        }

        // 4. generate next W tile
        if (cur + 1 < NTILES)
            gen8((mwB >> msh) & 0xffu, (cur + 1) * KT, WsA[ph ^ 1], r, jo, P2u, Q2u);
        mwB = mwC;

        // 5. single barrier: Bs arrived + gen visible
        CP_WAIT0();
        __syncthreads();
    }

    // ---- epilogue: publish row sums from ones-column acc, scale, ELU ----
    float* Ssum = reinterpret_cast<float*>(smem);
    __syncthreads();
    if (wid < 2 && (lane & 3) == 0) {
        int g = lane >> 2;
        Ssum[wm * 16 + g]     = acc_s[0];   // col 0 of ones tile = S, rows g / g+8
        Ssum[wm * 16 + g + 8] = acc_s[2];
    }
    __syncthreads();

    const int g    = lane >> 2;
    const int row0 = wm * 16 + g;
    const int row1 = row0 + 8;
    float inv0 = 1.f / Ssum[row0];
    float inv1 = 1.f / Ssum[row1];

#pragma unroll
    for (int bn = 0; bn < 2; bn++) {
        int cn = wn * 16 + bn * 8 + 2 * (lane & 3);
        size_t o0 = (size_t)(i0 + row0) * OUT_DIM + cn;
        size_t o1 = (size_t)(i0 + row1) * OUT_DIM + cn;
        float v0 = acc[bn][0] * inv0, v1 = acc[bn][1] * inv0;
        float v2 = acc[bn][2] * inv1, v3 = acc[bn][3] * inv1;
        float2 r01 = make_float2(v0 > 0.f ? v0 : __expf(v0) - 1.f,
                                 v1 > 0.f ? v1 : __expf(v1) - 1.f);
        float2 r23 = make_float2(v2 > 0.f ? v2 : __expf(v2) - 1.f,
                                 v3 > 0.f ? v3 : __expf(v3) - 1.f);
        *reinterpret_cast<float2*>(out + o0) = r01;
        *reinterpret_cast<float2*>(out + o1) = r23;
    }
}

// ---------------------------------------------------------------------------
extern "C" void kernel_launch(void* const* d_in, const int* in_sizes, int n_in,
                              void* d_out, int out_size) {
    const int*   adj = (const int*)d_in[0];
    const float* X   = (const float*)d_in[1];
    const float* W   = (const float*)d_in[2];
    const float* a   = (const float*)d_in[3];
    float* out = (float*)d_out;

    cudaFuncSetAttribute(k_main, cudaFuncAttributeMaxDynamicSharedMemorySize, SMEM_BYTES);

    k_pre<<<WH_BLOCKS + N_NODES, 256>>>(X, W, a, adj);
    k_max<<<1, 256>>>();
    k_prep2<<<N_NODES / 256, 256>>>();
    k_main<<<N_NODES / MT, NTHREADS, SMEM_BYTES>>>(out);
}